// round 2
// baseline (speedup 1.0000x reference)
#include <cuda_runtime.h>
#include <math.h>

#define BATCH 4
#define SPAST 1024
#define SFUT 512
#define NTOK 1536
#define DM 256
#define NH 8
#define DH 32
#define DFF 2048
#define NLAYERS 8
#define NROWS (BATCH*NTOK)        // 6144
#define CHUNK 128
#define NCHUNK (NTOK/CHUNK)       // 12
#define NBH (BATCH*NH)            // 32

typedef unsigned long long ull;

// ---------------- scratch (no allocation allowed) ----------------
__device__ float g_x  [NROWS*DM];
__device__ float g_qb [NROWS*DM];
__device__ float g_kb [NROWS*DM];
__device__ float g_vb [NROWS*DM];
__device__ float g_ab [NROWS*DM];
__device__ float g_hb [NROWS*DFF];
__device__ float g_part[4*NROWS*DM];
__device__ float g_Sloc[NBH*NCHUNK*DH*DH];
__device__ float g_Spre[NBH*NCHUNK*DH*DH];
__device__ float g_kloc[NBH*NCHUNK*DH];
__device__ float g_kpre[NBH*NCHUNK*DH];

// ---------------- packed fp32x2 helpers (sm_103a) ----------------
__device__ __forceinline__ ull pack2(float v){
    ull r; unsigned int u = __float_as_uint(v);
    asm("mov.b64 %0, {%1, %1};" : "=l"(r) : "r"(u));
    return r;
}
__device__ __forceinline__ void fma2(ull &d, ull a, ull b){
    asm("fma.rn.f32x2 %0, %1, %2, %0;" : "+l"(d) : "l"(a), "l"(b));
}
__device__ __forceinline__ float2 unp2(ull v){
    unsigned int lo, hi;
    asm("mov.b64 {%0, %1}, %2;" : "=r"(lo), "=r"(hi) : "l"(v));
    return make_float2(__uint_as_float(lo), __uint_as_float(hi));
}

// ---------------- embedding ----------------
__global__ void embed_kernel(const float* __restrict__ px, const float* __restrict__ py,
                             const float* __restrict__ fx,
                             const float* __restrict__ W, const float* __restrict__ b,
                             float* __restrict__ x)
{
    __shared__ float s[24];
    int r = blockIdx.x;
    int bb = r / NTOK, n = r % NTOK;
    int t = threadIdx.x;
    if (t < 24) {
        float v;
        if (t < 16) {
            v = (n < SPAST) ? px[(bb*SPAST+n)*16+t] : fx[(bb*SFUT+(n-SPAST))*16+t];
        } else {
            int yn = (n < SPAST) ? n : (SPAST-1);
            v = py[(bb*SPAST+yn)*8 + (t-16)];
        }
        s[t] = v;
    }
    __syncthreads();
    float acc = b[t];
    #pragma unroll
    for (int kk=0; kk<24; kk++) acc = fmaf(s[kk], W[kk*DM+t], acc);
    x[(size_t)r*DM + t] = acc;
}

// ---------------- GEMM core: double-buffered, packed fp32x2 ----------------
// EPI: 0 = +bias, 1 = elu(x+bias)+1, 2 = relu(x+bias), 3 = +bias+res, 4 = raw
#define GBM 128
#define GBN 64
#define GBK 16

__device__ __forceinline__ void gemm_body(
    int K, int N, int kbeg, int nk,
    const float* __restrict__ A, const float* __restrict__ B,
    const float* __restrict__ bias, const float* __restrict__ res,
    float* __restrict__ C, int epi)
{
    __shared__ float As[2][GBK][GBM+4];     // transposed A, 16B-aligned rows
    __shared__ ull   Bsd[2][GBK][GBN];      // B with each float duplicated into both lanes

    const int t  = threadIdx.x;
    const int tx = t & 15;                  // N dir
    const int ty = t >> 4;                  // M dir
    const int bm = blockIdx.y * GBM;
    const int bn = blockIdx.x * GBN;

    const int arow = t >> 2;                // 0..63
    const int akq  = (t & 3) * 4;           // k offset within tile
    const int brow = t >> 4;                // 0..15
    const int bcol = (t & 15) * 4;

    const float* Aptr = A + (size_t)bm*K + kbeg + akq;
    const float* Bptr = B + (size_t)(kbeg+brow)*N + bn + bcol;

    // stage tile 0
    float4 a0 = *(const float4*)(Aptr + (size_t)arow*K);
    float4 a1 = *(const float4*)(Aptr + (size_t)(arow+64)*K);
    float4 b0 = *(const float4*)Bptr;
    {
        As[0][akq+0][arow]=a0.x; As[0][akq+1][arow]=a0.y; As[0][akq+2][arow]=a0.z; As[0][akq+3][arow]=a0.w;
        As[0][akq+0][arow+64]=a1.x; As[0][akq+1][arow+64]=a1.y; As[0][akq+2][arow+64]=a1.z; As[0][akq+3][arow+64]=a1.w;
        ulonglong2* bp = (ulonglong2*)&Bsd[0][brow][bcol];
        ulonglong2 w0; w0.x = pack2(b0.x); w0.y = pack2(b0.y);
        ulonglong2 w1; w1.x = pack2(b0.z); w1.y = pack2(b0.w);
        bp[0] = w0; bp[1] = w1;
    }
    __syncthreads();

    ull acc[4][4];
    #pragma unroll
    for (int p=0;p<4;p++)
        #pragma unroll
        for (int j=0;j<4;j++) acc[p][j] = 0ull;

    for (int kt=0; kt<nk; kt++){
        const int buf = kt & 1;
        float4 na0, na1, nb0;
        const bool more = (kt+1 < nk);
        if (more){
            const float* Ap = Aptr + (kt+1)*GBK;
            na0 = *(const float4*)(Ap + (size_t)arow*K);
            na1 = *(const float4*)(Ap + (size_t)(arow+64)*K);
            nb0 = *(const float4*)(Bptr + (size_t)(kt+1)*GBK*N);
        }
        #pragma unroll
        for (int kk=0;kk<GBK;kk++){
            const ulonglong2* ap = (const ulonglong2*)&As[buf][kk][ty*8];
            ulonglong2 aA = ap[0], aB = ap[1];
            const ulonglong2* bp = (const ulonglong2*)&Bsd[buf][kk][tx*4];
            ulonglong2 bA = bp[0], bB = bp[1];
            ull a2[4] = {aA.x, aA.y, aB.x, aB.y};
            ull b2[4] = {bA.x, bA.y, bB.x, bB.y};
            #pragma unroll
            for (int p=0;p<4;p++)
                #pragma unroll
                for (int j=0;j<4;j++) fma2(acc[p][j], a2[p], b2[j]);
        }
        if (more){
            const int nb = buf ^ 1;
            As[nb][akq+0][arow]=na0.x; As[nb][akq+1][arow]=na0.y; As[nb][akq+2][arow]=na0.z; As[nb][akq+3][arow]=na0.w;
            As[nb][akq+0][arow+64]=na1.x; As[nb][akq+1][arow+64]=na1.y; As[nb][akq+2][arow+64]=na1.z; As[nb][akq+3][arow+64]=na1.w;
            ulonglong2* bpw = (ulonglong2*)&Bsd[nb][brow][bcol];
            ulonglong2 w0; w0.x = pack2(nb0.x); w0.y = pack2(nb0.y);
            ulonglong2 w1; w1.x = pack2(nb0.z); w1.y = pack2(nb0.w);
            bpw[0] = w0; bpw[1] = w1;
        }
        __syncthreads();
    }

    #pragma unroll
    for (int p=0;p<4;p++){
        float2 u[4];
        #pragma unroll
        for (int j=0;j<4;j++) u[j] = unp2(acc[p][j]);
        #pragma unroll
        for (int half=0; half<2; half++){
            int row = bm + ty*8 + 2*p + half;
            float cv[4];
            #pragma unroll
            for (int j=0;j<4;j++){
                float vv = (half==0)? u[j].x : u[j].y;
                int col = bn + tx*4 + j;
                if (epi != 4) vv += bias[col];
                if (epi == 1) vv = (vv>=0.f)? vv+1.f : expf(vv);   // elu(x)+1
                if (epi == 2) vv = fmaxf(vv, 0.f);
                if (epi == 3) vv += res[(size_t)row*N + col];
                cv[j]=vv;
            }
            float4 o; o.x=cv[0]; o.y=cv[1]; o.z=cv[2]; o.w=cv[3];
            *(float4*)(C + (size_t)row*N + bn + tx*4) = o;
        }
    }
}

__global__ void __launch_bounds__(256) sgemm_kernel(
    int K, int N, int ksplit,
    const float* __restrict__ A, const float* __restrict__ B,
    const float* __restrict__ bias, const float* __restrict__ res,
    float* __restrict__ C, int epi, size_t cstride)
{
    int z = blockIdx.z;
    gemm_body(K, N, z*ksplit, ksplit/GBK, A, B, bias, res, C + (size_t)z*cstride, epi);
}

__global__ void __launch_bounds__(256) qkv_kernel(
    const float* __restrict__ x,
    const float* __restrict__ Wq, const float* __restrict__ bq,
    const float* __restrict__ Wk, const float* __restrict__ bk,
    const float* __restrict__ Wv, const float* __restrict__ bv,
    float* __restrict__ q, float* __restrict__ k, float* __restrict__ v)
{
    int z = blockIdx.z;
    const float* W = (z==0)? Wq : (z==1)? Wk : Wv;
    const float* b = (z==0)? bq : (z==1)? bk : bv;
    float* out     = (z==0)? q  : (z==1)? k  : v;
    gemm_body(DM, DM, 0, DM/GBK, x, W, b, nullptr, out, (z==2)?0:1);
}

// ---------------- per-chunk K^T V state + K column sums ----------------
__global__ void __launch_bounds__(1024) chunk_kv_kernel(const float* __restrict__ k,
                                                        const float* __restrict__ v)
{
    int c = blockIdx.x, bh = blockIdx.y;
    int b = bh >> 3, h = bh & 7;
    __shared__ float ks[CHUNK][DH];
    __shared__ float vs[CHUNK][DH];
    int t = threadIdx.x;
    int base = b*NTOK + c*CHUNK;
    for (int idx=t; idx<CHUNK*DH; idx+=1024){
        int row = idx >> 5, col = idx & 31;
        size_t g = (size_t)(base+row)*DM + h*DH + col;
        ks[row][col] = k[g];
        vs[row][col] = v[g];
    }
    __syncthreads();
    int d = t >> 5, m = t & 31;
    float s = 0.f;
    #pragma unroll 8
    for (int j=0;j<CHUNK;j++) s = fmaf(ks[j][d], vs[j][m], s);
    g_Sloc[((size_t)bh*NCHUNK + c)*DH*DH + d*DH + m] = s;
    if (t < DH){
        float kssum = 0.f;
        #pragma unroll 8
        for (int j=0;j<CHUNK;j++) kssum += ks[j][t];
        g_kloc[((size_t)bh*NCHUNK + c)*DH + t] = kssum;
    }
}

// ---------------- exclusive prefix over chunks ----------------
__global__ void __launch_bounds__(1024) scan_kernel()
{
    int bh = blockIdx.x, t = threadIdx.x;
    float acc = 0.f;
    for (int c=0;c<NCHUNK;c++){
        size_t o = ((size_t)bh*NCHUNK + c)*DH*DH + t;
        g_Spre[o] = acc; acc += g_Sloc[o];
    }
    if (t < DH){
        float a2 = 0.f;
        for (int c=0;c<NCHUNK;c++){
            size_t o = ((size_t)bh*NCHUNK + c)*DH + t;
            g_kpre[o] = a2; a2 += g_kloc[o];
        }
    }
}

// ---------------- attention output ----------------
__global__ void __launch_bounds__(128) attn_kernel(const float* __restrict__ q,
                                                   const float* __restrict__ k,
                                                   const float* __restrict__ v,
                                                   float* __restrict__ a)
{
    int c = blockIdx.x, bh = blockIdx.y;
    int b = bh >> 3, h = bh & 7;
    __shared__ float ks[CHUNK][DH];
    __shared__ float vs[CHUNK][DH];
    __shared__ float Ss[DH][DH];
    __shared__ float kss[DH];
    int t = threadIdx.x;
    int base = b*NTOK + c*CHUNK;
    for (int idx=t; idx<CHUNK*DH; idx+=128){
        int row = idx >> 5, col = idx & 31;
        size_t g = (size_t)(base+row)*DM + h*DH + col;
        ks[row][col] = k[g];
        vs[row][col] = v[g];
    }
    for (int idx=t; idx<DH*DH; idx+=128)
        Ss[idx>>5][idx&31] = g_Spre[((size_t)bh*NCHUNK + c)*DH*DH + idx];
    if (t < DH) kss[t] = g_kpre[((size_t)bh*NCHUNK + c)*DH + t];
    __syncthreads();

    float qr[DH], num[DH];
    {
        const float4* qp = (const float4*)(q + (size_t)(base+t)*DM + h*DH);
        #pragma unroll
        for (int d4=0; d4<8; d4++){
            float4 w4 = qp[d4];
            qr[4*d4+0]=w4.x; qr[4*d4+1]=w4.y; qr[4*d4+2]=w4.z; qr[4*d4+3]=w4.w;
        }
    }
    #pragma unroll
    for (int m=0;m<DH;m++) num[m] = 0.f;
    float z = 0.f;

    #pragma unroll
    for (int d=0; d<DH; d++){
        float qa = qr[d];
        z = fmaf(qa, kss[d], z);
        #pragma unroll
        for (int m=0;m<DH;m++) num[m] = fmaf(qa, Ss[d][m], num[m]);
    }
    int jend = t | 31;
    for (int j=0; j<=jend; j++){
        float aa = 0.f;
        #pragma unroll
        for (int d=0; d<DH; d++) aa = fmaf(qr[d], ks[j][d], aa);
        aa = (j <= t) ? aa : 0.f;
        z += aa;
        #pragma unroll
        for (int m=0;m<DH;m++) num[m] = fmaf(aa, vs[j][m], num[m]);
    }
    float inv = 1.f / (z + 1e-6f);
    float4* op = (float4*)(a + (size_t)(base+t)*DM + h*DH);
    #pragma unroll
    for (int d4=0; d4<8; d4++)
        op[d4] = make_float4(num[4*d4]*inv, num[4*d4+1]*inv, num[4*d4+2]*inv, num[4*d4+3]*inv);
}

// ---------------- residual + split-K reduce + LayerNorm (fused) ----------------
__global__ void __launch_bounds__(256) ln_red_kernel(
    int np, const float* __restrict__ part, size_t pstride,
    const float* __restrict__ xin, const float* __restrict__ bias,
    const float* __restrict__ w, const float* __restrict__ b,
    float* __restrict__ out)
{
    __shared__ float red[8], red2[8];
    int r = blockIdx.x, t = threadIdx.x;
    size_t o = (size_t)r*DM + t;
    float v = xin[o] + bias[t];
    for (int i=0;i<np;i++) v += part[(size_t)i*pstride + o];
    float s = v, s2 = v*v;
    #pragma unroll
    for (int off=16;off;off>>=1){ s += __shfl_xor_sync(~0u,s,off); s2 += __shfl_xor_sync(~0u,s2,off); }
    int warp = t >> 5, lane = t & 31;
    if (lane == 0){ red[warp] = s; red2[warp] = s2; }
    __syncthreads();
    float S=0.f, S2=0.f;
    #pragma unroll
    for (int i=0;i<8;i++){ S += red[i]; S2 += red2[i]; }
    float mean = S * (1.f/DM);
    float var  = S2 * (1.f/DM) - mean*mean;
    out[o] = (v - mean) * rsqrtf(var + 1e-5f) * w[t] + b[t];
}

// ---------------- head: mean / sigma ----------------
__global__ void __launch_bounds__(256) head_kernel(const float* __restrict__ x,
                                                   const float* __restrict__ mW, const float* __restrict__ mb,
                                                   const float* __restrict__ sW, const float* __restrict__ sb,
                                                   float* __restrict__ out)
{
    __shared__ float sx[DM];
    int r = blockIdx.x;
    int b = r / SFUT, s = r % SFUT;
    const float* xr = x + (size_t)(b*NTOK + SPAST + s)*DM;
    int t = threadIdx.x;
    sx[t] = xr[t];
    __syncthreads();
    int warp = t >> 5, lane = t & 31;
    float am = 0.f, as = 0.f;
    for (int kk=lane; kk<DM; kk+=32){
        float xv = sx[kk];
        am = fmaf(xv, mW[kk*8 + warp], am);
        as = fmaf(xv, sW[kk*8 + warp], as);
    }
    #pragma unroll
    for (int off=16;off;off>>=1){ am += __shfl_xor_sync(~0u,am,off); as += __shfl_xor_sync(~0u,as,off); }
    if (lane == 0){
        int o = r*8 + warp;
        out[o] = am + mb[warp];
        float sp = as + sb[warp];
        float spv = (sp > 20.f) ? sp : log1pf(expf(sp));
        out[BATCH*SFUT*8 + o] = 0.01f + 0.99f*spv;
    }
}

// ---------------- launch ----------------
extern "C" void kernel_launch(void* const* d_in, const int* in_sizes, int n_in,
                              void* d_out, int out_size)
{
    (void)in_sizes; (void)n_in; (void)out_size;
    const float* past_x   = (const float*)d_in[0];
    const float* past_y   = (const float*)d_in[1];
    const float* future_x = (const float*)d_in[2];
    const float* enc_W    = (const float*)d_in[3];
    const float* enc_b    = (const float*)d_in[4];
    const float* Wq  = (const float*)d_in[5];  const float* bq  = (const float*)d_in[6];
    const float* Wk  = (const float*)d_in[7];  const float* bk  = (const float*)d_in[8];
    const float* Wv  = (const float*)d_in[9];  const float* bv  = (const float*)d_in[10];
    const float* Wo  = (const float*)d_in[11]; const float* bo  = (const float*)d_in[12];
    const float* ln1w= (const float*)d_in[13]; const float* ln1b= (const float*)d_in[14];
    const float* W1  = (const float*)d_in[15]; const float* b1  = (const float*)d_in[16];
    const float* W2  = (const float*)d_in[17]; const float* b2  = (const float*)d_in[18];
    const float* ln2w= (const float*)d_in[19]; const float* ln2b= (const float*)d_in[20];
    const float* mW  = (const float*)d_in[21]; const float* mb  = (const float*)d_in[22];
    const float* sW  = (const float*)d_in[23]; const float* sb  = (const float*)d_in[24];

    float *x,*q,*k,*v,*a,*h,*part;
    cudaGetSymbolAddress((void**)&x,   g_x);
    cudaGetSymbolAddress((void**)&q,   g_qb);
    cudaGetSymbolAddress((void**)&k,   g_kb);
    cudaGetSymbolAddress((void**)&v,   g_vb);
    cudaGetSymbolAddress((void**)&a,   g_ab);
    cudaGetSymbolAddress((void**)&h,   g_hb);
    cudaGetSymbolAddress((void**)&part,g_part);

    embed_kernel<<<NROWS, 256>>>(past_x, past_y, future_x, enc_W, enc_b, x);

    dim3 gQKV(DM/GBN,  NROWS/GBM, 3);   // 4 x 48 x 3
    dim3 gWo (DM/GBN,  NROWS/GBM, 2);   // split-K 2
    dim3 gFF (DFF/GBN, NROWS/GBM, 1);   // 32 x 48
    dim3 gW2 (DM/GBN,  NROWS/GBM, 4);   // split-K 4
    dim3 gA  (NCHUNK, NBH);

    const size_t PS = (size_t)NROWS*DM;

    for (int i=0;i<NLAYERS;i++){
        const float* wq = Wq + (size_t)i*DM*DM;  const float* vbq = bq + i*DM;
        const float* wk = Wk + (size_t)i*DM*DM;  const float* vbk = bk + i*DM;
        const float* wv = Wv + (size_t)i*DM*DM;  const float* vbv = bv + i*DM;
        const float* wo = Wo + (size_t)i*DM*DM;  const float* vbo = bo + i*DM;
        const float* w1 = W1 + (size_t)i*DM*DFF; const float* vb1 = b1 + i*DFF;
        const float* w2 = W2 + (size_t)i*DFF*DM; const float* vb2 = b2 + i*DM;

        qkv_kernel<<<gQKV, 256>>>(x, wq, vbq, wk, vbk, wv, vbv, q, k, v);

        chunk_kv_kernel<<<gA, 1024>>>(k, v);
        scan_kernel<<<NBH, 1024>>>();
        attn_kernel<<<gA, 128>>>(q, k, v, a);

        // Wo: split-K=2 into partials, then fused residual+reduce+LN -> x
        sgemm_kernel<<<gWo, 256>>>(DM, DM, DM/2, a, wo, nullptr, nullptr, part, 4, PS);
        ln_red_kernel<<<NROWS, 256>>>(2, part, PS, x, vbo, ln1w + i*DM, ln1b + i*DM, x);

        // FFN
        sgemm_kernel<<<gFF, 256>>>(DM, DFF, DM, x, w1, vb1, nullptr, h, 2, 0);
        sgemm_kernel<<<gW2, 256>>>(DFF, DM, DFF/4, h, w2, nullptr, nullptr, part, 4, PS);
        ln_red_kernel<<<NROWS, 256>>>(4, part, PS, x, vb2, ln2w + i*DM, ln2b + i*DM, x);
    }

    head_kernel<<<BATCH*SFUT, 256>>>(x, mW, mb, sW, sb, (float*)d_out);
}

// round 3
// speedup vs baseline: 1.7327x; 1.7327x over previous
#include <cuda_runtime.h>
#include <math.h>

#define BATCH 4
#define SPAST 1024
#define SFUT 512
#define NTOK 1536
#define DM 256
#define NH 8
#define DH 32
#define DFF 2048
#define NLAYERS 8
#define NROWS (BATCH*NTOK)        // 6144
#define CHUNK 128
#define NCHUNK (NTOK/CHUNK)       // 12
#define NBH (BATCH*NH)            // 32

typedef unsigned long long ull;

// ---------------- scratch (no allocation allowed) ----------------
__device__ float g_x  [NROWS*DM];
__device__ float g_qb [NROWS*DM];
__device__ float g_kb [NROWS*DM];
__device__ float g_vb [NROWS*DM];
__device__ float g_ab [NROWS*DM];
__device__ float g_hb [NROWS*DFF];
__device__ float g_part[4*NROWS*DM];
__device__ float g_Sloc[NBH*NCHUNK*DH*DH];
__device__ float g_kloc[NBH*NCHUNK*DH];

// ---------------- packed fp32x2 helpers (sm_103a) ----------------
__device__ __forceinline__ ull pack2(float v){
    ull r; unsigned int u = __float_as_uint(v);
    asm("mov.b64 %0, {%1, %1};" : "=l"(r) : "r"(u));
    return r;
}
__device__ __forceinline__ void fma2(ull &d, ull a, ull b){
    asm("fma.rn.f32x2 %0, %1, %2, %0;" : "+l"(d) : "l"(a), "l"(b));
}
__device__ __forceinline__ float2 unp2(ull v){
    unsigned int lo, hi;
    asm("mov.b64 {%0, %1}, %2;" : "=r"(lo), "=r"(hi) : "l"(v));
    return make_float2(__uint_as_float(lo), __uint_as_float(hi));
}

// ---------------- embedding ----------------
__global__ void embed_kernel(const float* __restrict__ px, const float* __restrict__ py,
                             const float* __restrict__ fx,
                             const float* __restrict__ W, const float* __restrict__ b,
                             float* __restrict__ x)
{
    __shared__ float s[24];
    int r = blockIdx.x;
    int bb = r / NTOK, n = r % NTOK;
    int t = threadIdx.x;
    if (t < 24) {
        float v;
        if (t < 16) {
            v = (n < SPAST) ? px[(bb*SPAST+n)*16+t] : fx[(bb*SFUT+(n-SPAST))*16+t];
        } else {
            int yn = (n < SPAST) ? n : (SPAST-1);
            v = py[(bb*SPAST+yn)*8 + (t-16)];
        }
        s[t] = v;
    }
    __syncthreads();
    float acc = b[t];
    #pragma unroll
    for (int kk=0; kk<24; kk++) acc = fmaf(s[kk], W[kk*DM+t], acc);
    x[(size_t)r*DM + t] = acc;
}

// ---------------- GEMM core (R1-proven body, single-buffered) ----------------
// EPI: 0 = +bias, 1 = elu(x+bias)+1, 2 = relu(x+bias), 3 = +bias+res, 4 = raw (no bias)
#define GBM 128
#define GBN 64
#define GBK 16

template<int EPI>
__device__ __forceinline__ void gemm_body(
    int K, int N, int kbeg, int kend,
    const float* __restrict__ A, const float* __restrict__ B,
    const float* __restrict__ bias, const float* __restrict__ res,
    float* __restrict__ C)
{
    __shared__ float As[GBK][GBM+2];   // A transposed, +2 pad
    __shared__ float Bs[GBK][GBN];
    const int t  = threadIdx.x;
    const int tx = t & 15;             // N direction
    const int ty = t >> 4;             // M direction
    const int bm = blockIdx.y * GBM;
    const int bn = blockIdx.x * GBN;

    ull acc[4][4];
    #pragma unroll
    for (int p=0;p<4;p++)
        #pragma unroll
        for (int j=0;j<4;j++) acc[p][j] = 0ull;

    const int arow0 = t >> 2;          // 0..63
    const int akq   = (t & 3) * 4;     // k offset 0,4,8,12
    const int brow  = t >> 4;          // 0..15
    const int bcol  = (t & 15) * 4;

    for (int k0=kbeg; k0<kend; k0+=GBK){
        #pragma unroll
        for (int l=0;l<2;l++){
            int row = arow0 + l*64;
            float4 av = *(const float4*)(A + (size_t)(bm+row)*K + k0 + akq);
            As[akq+0][row]=av.x; As[akq+1][row]=av.y; As[akq+2][row]=av.z; As[akq+3][row]=av.w;
        }
        *(float4*)&Bs[brow][bcol] = *(const float4*)(B + (size_t)(k0+brow)*N + bn + bcol);
        __syncthreads();
        #pragma unroll
        for (int kk=0;kk<GBK;kk++){
            const ull* arow = (const ull*)&As[kk][0];
            ull a2[4];
            #pragma unroll
            for (int p=0;p<4;p++) a2[p] = arow[ty*4+p];
            ull bb2[4];
            #pragma unroll
            for (int j=0;j<4;j++) bb2[j] = pack2(Bs[kk][tx*4+j]);
            #pragma unroll
            for (int p=0;p<4;p++)
                #pragma unroll
                for (int j=0;j<4;j++) fma2(acc[p][j], a2[p], bb2[j]);
        }
        __syncthreads();
    }

    #pragma unroll
    for (int p=0;p<4;p++){
        float2 u[4];
        #pragma unroll
        for (int j=0;j<4;j++) u[j] = unp2(acc[p][j]);
        #pragma unroll
        for (int half=0; half<2; half++){
            int row = bm + ty*8 + 2*p + half;
            float cv[4];
            #pragma unroll
            for (int j=0;j<4;j++){
                float vv = (half==0)? u[j].x : u[j].y;
                int col = bn + tx*4 + j;
                if (EPI != 4) vv += bias[col];
                if (EPI == 1) vv = (vv>=0.f)? vv+1.f : expf(vv);   // elu(x)+1
                if (EPI == 2) vv = fmaxf(vv, 0.f);
                if (EPI == 3) vv += res[(size_t)row*N + col];
                cv[j]=vv;
            }
            float4 o; o.x=cv[0]; o.y=cv[1]; o.z=cv[2]; o.w=cv[3];
            *(float4*)(C + (size_t)row*N + bn + tx*4) = o;
        }
    }
}

// plain GEMM, optional split-K via blockIdx.z writing partial buffers
template<int EPI>
__global__ void __launch_bounds__(256) sgemm_kernel(
    int K, int N, int ksplit,
    const float* __restrict__ A, const float* __restrict__ B,
    const float* __restrict__ bias, const float* __restrict__ res,
    float* __restrict__ C, size_t cstride)
{
    int z = blockIdx.z;
    gemm_body<EPI>(K, N, z*ksplit, (z+1)*ksplit, A, B, bias, res, C + (size_t)z*cstride);
}

// fused Q/K/V: z selects weight/bias/output and epilogue
__global__ void __launch_bounds__(256) qkv_kernel(
    const float* __restrict__ x,
    const float* __restrict__ Wq, const float* __restrict__ bq,
    const float* __restrict__ Wk, const float* __restrict__ bk,
    const float* __restrict__ Wv, const float* __restrict__ bv,
    float* __restrict__ q, float* __restrict__ k, float* __restrict__ v)
{
    int z = blockIdx.z;
    if (z == 0)      gemm_body<1>(DM, DM, 0, DM, x, Wq, bq, nullptr, q);
    else if (z == 1) gemm_body<1>(DM, DM, 0, DM, x, Wk, bk, nullptr, k);
    else             gemm_body<0>(DM, DM, 0, DM, x, Wv, bv, nullptr, v);
}

// ---------------- per-chunk K^T V state + K column sums ----------------
__global__ void __launch_bounds__(1024) chunk_kv_kernel(const float* __restrict__ k,
                                                        const float* __restrict__ v)
{
    int c = blockIdx.x, bh = blockIdx.y;
    int b = bh >> 3, h = bh & 7;
    __shared__ float ks[CHUNK][DH];
    __shared__ float vs[CHUNK][DH];
    int t = threadIdx.x;
    int base = b*NTOK + c*CHUNK;
    for (int idx=t; idx<CHUNK*DH; idx+=1024){
        int row = idx >> 5, col = idx & 31;
        size_t g = (size_t)(base+row)*DM + h*DH + col;
        ks[row][col] = k[g];
        vs[row][col] = v[g];
    }
    __syncthreads();
    int d = t >> 5, m = t & 31;
    float s = 0.f;
    #pragma unroll 8
    for (int j=0;j<CHUNK;j++) s = fmaf(ks[j][d], vs[j][m], s);
    g_Sloc[((size_t)bh*NCHUNK + c)*DH*DH + d*DH + m] = s;
    if (t < DH){
        float kssum = 0.f;
        #pragma unroll 8
        for (int j=0;j<CHUNK;j++) kssum += ks[j][t];
        g_kloc[((size_t)bh*NCHUNK + c)*DH + t] = kssum;
    }
}

// ---------------- attention output (inline chunk-prefix over Sloc/kloc) ----------------
__global__ void __launch_bounds__(128) attn_kernel(const float* __restrict__ q,
                                                   const float* __restrict__ k,
                                                   const float* __restrict__ v,
                                                   float* __restrict__ a)
{
    int c = blockIdx.x, bh = blockIdx.y;
    int b = bh >> 3, h = bh & 7;
    __shared__ float ks[CHUNK][DH];
    __shared__ float vs[CHUNK][DH];
    __shared__ float Ss[DH][DH];
    __shared__ float kss[DH];
    int t = threadIdx.x;
    int base = b*NTOK + c*CHUNK;
    for (int idx=t; idx<CHUNK*DH; idx+=128){
        int row = idx >> 5, col = idx & 31;
        size_t g = (size_t)(base+row)*DM + h*DH + col;
        ks[row][col] = k[g];
        vs[row][col] = v[g];
    }
    // exclusive prefix of chunk states, computed inline (c <= 11 chunks, L2-resident)
    for (int idx=t; idx<DH*DH; idx+=128){
        float s = 0.f;
        const float* p = g_Sloc + (size_t)bh*NCHUNK*DH*DH + idx;
        for (int cc=0; cc<c; cc++) s += p[cc*DH*DH];
        Ss[idx>>5][idx&31] = s;
    }
    if (t < DH){
        float s = 0.f;
        const float* p = g_kloc + (size_t)bh*NCHUNK*DH + t;
        for (int cc=0; cc<c; cc++) s += p[cc*DH];
        kss[t] = s;
    }
    __syncthreads();

    float qr[DH], num[DH];
    {
        const float4* qp = (const float4*)(q + (size_t)(base+t)*DM + h*DH);
        #pragma unroll
        for (int d4=0; d4<8; d4++){
            float4 w4 = qp[d4];
            qr[4*d4+0]=w4.x; qr[4*d4+1]=w4.y; qr[4*d4+2]=w4.z; qr[4*d4+3]=w4.w;
        }
    }
    #pragma unroll
    for (int m=0;m<DH;m++) num[m] = 0.f;
    float z = 0.f;

    #pragma unroll
    for (int d=0; d<DH; d++){
        float qa = qr[d];
        z = fmaf(qa, kss[d], z);
        #pragma unroll
        for (int m=0;m<DH;m++) num[m] = fmaf(qa, Ss[d][m], num[m]);
    }
    int jend = t | 31;
    for (int j=0; j<=jend; j++){
        float aa = 0.f;
        #pragma unroll
        for (int d=0; d<DH; d++) aa = fmaf(qr[d], ks[j][d], aa);
        aa = (j <= t) ? aa : 0.f;
        z += aa;
        #pragma unroll
        for (int m=0;m<DH;m++) num[m] = fmaf(aa, vs[j][m], num[m]);
    }
    float inv = 1.f / (z + 1e-6f);
    float4* op = (float4*)(a + (size_t)(base+t)*DM + h*DH);
    #pragma unroll
    for (int d4=0; d4<8; d4++)
        op[d4] = make_float4(num[4*d4]*inv, num[4*d4+1]*inv, num[4*d4+2]*inv, num[4*d4+3]*inv);
}

// ---------------- residual + split-K reduce + LayerNorm (fused) ----------------
__global__ void __launch_bounds__(256) ln_red_kernel(
    int np, const float* __restrict__ part, size_t pstride,
    const float* __restrict__ xin, const float* __restrict__ bias,
    const float* __restrict__ w, const float* __restrict__ b,
    float* __restrict__ out)
{
    __shared__ float red[8], red2[8];
    int r = blockIdx.x, t = threadIdx.x;
    size_t o = (size_t)r*DM + t;
    float v = xin[o] + bias[t];
    for (int i=0;i<np;i++) v += part[(size_t)i*pstride + o];
    float s = v, s2 = v*v;
    #pragma unroll
    for (int off=16;off;off>>=1){ s += __shfl_xor_sync(~0u,s,off); s2 += __shfl_xor_sync(~0u,s2,off); }
    int warp = t >> 5, lane = t & 31;
    if (lane == 0){ red[warp] = s; red2[warp] = s2; }
    __syncthreads();
    float S=0.f, S2=0.f;
    #pragma unroll
    for (int i=0;i<8;i++){ S += red[i]; S2 += red2[i]; }
    float mean = S * (1.f/DM);
    float var  = S2 * (1.f/DM) - mean*mean;
    out[o] = (v - mean) * rsqrtf(var + 1e-5f) * w[t] + b[t];
}

// ---------------- head: mean / sigma ----------------
__global__ void __launch_bounds__(256) head_kernel(const float* __restrict__ x,
                                                   const float* __restrict__ mW, const float* __restrict__ mb,
                                                   const float* __restrict__ sW, const float* __restrict__ sb,
                                                   float* __restrict__ out)
{
    __shared__ float sx[DM];
    int r = blockIdx.x;
    int b = r / SFUT, s = r % SFUT;
    const float* xr = x + (size_t)(b*NTOK + SPAST + s)*DM;
    int t = threadIdx.x;
    sx[t] = xr[t];
    __syncthreads();
    int warp = t >> 5, lane = t & 31;
    float am = 0.f, as = 0.f;
    for (int kk=lane; kk<DM; kk+=32){
        float xv = sx[kk];
        am = fmaf(xv, mW[kk*8 + warp], am);
        as = fmaf(xv, sW[kk*8 + warp], as);
    }
    #pragma unroll
    for (int off=16;off;off>>=1){ am += __shfl_xor_sync(~0u,am,off); as += __shfl_xor_sync(~0u,as,off); }
    if (lane == 0){
        int o = r*8 + warp;
        out[o] = am + mb[warp];
        float sp = as + sb[warp];
        float spv = (sp > 20.f) ? sp : log1pf(expf(sp));
        out[BATCH*SFUT*8 + o] = 0.01f + 0.99f*spv;
    }
}

// ---------------- launch ----------------
extern "C" void kernel_launch(void* const* d_in, const int* in_sizes, int n_in,
                              void* d_out, int out_size)
{
    (void)in_sizes; (void)n_in; (void)out_size;
    const float* past_x   = (const float*)d_in[0];
    const float* past_y   = (const float*)d_in[1];
    const float* future_x = (const float*)d_in[2];
    const float* enc_W    = (const float*)d_in[3];
    const float* enc_b    = (const float*)d_in[4];
    const float* Wq  = (const float*)d_in[5];  const float* bq  = (const float*)d_in[6];
    const float* Wk  = (const float*)d_in[7];  const float* bk  = (const float*)d_in[8];
    const float* Wv  = (const float*)d_in[9];  const float* bv  = (const float*)d_in[10];
    const float* Wo  = (const float*)d_in[11]; const float* bo  = (const float*)d_in[12];
    const float* ln1w= (const float*)d_in[13]; const float* ln1b= (const float*)d_in[14];
    const float* W1  = (const float*)d_in[15]; const float* b1  = (const float*)d_in[16];
    const float* W2  = (const float*)d_in[17]; const float* b2  = (const float*)d_in[18];
    const float* ln2w= (const float*)d_in[19]; const float* ln2b= (const float*)d_in[20];
    const float* mW  = (const float*)d_in[21]; const float* mb  = (const float*)d_in[22];
    const float* sW  = (const float*)d_in[23]; const float* sb  = (const float*)d_in[24];

    float *x,*q,*k,*v,*a,*h,*part;
    cudaGetSymbolAddress((void**)&x,   g_x);
    cudaGetSymbolAddress((void**)&q,   g_qb);
    cudaGetSymbolAddress((void**)&k,   g_kb);
    cudaGetSymbolAddress((void**)&v,   g_vb);
    cudaGetSymbolAddress((void**)&a,   g_ab);
    cudaGetSymbolAddress((void**)&h,   g_hb);
    cudaGetSymbolAddress((void**)&part,g_part);

    embed_kernel<<<NROWS, 256>>>(past_x, past_y, future_x, enc_W, enc_b, x);

    dim3 gQKV(DM/GBN,  NROWS/GBM, 3);   // 4 x 48 x 3 = 576 blocks
    dim3 gWo (DM/GBN,  NROWS/GBM, 2);   // split-K 2 -> 384 blocks
    dim3 gFF (DFF/GBN, NROWS/GBM, 1);   // 32 x 48 = 1536 blocks
    dim3 gW2 (DM/GBN,  NROWS/GBM, 4);   // split-K 4 -> 768 blocks
    dim3 gA  (NCHUNK, NBH);

    const size_t PS = (size_t)NROWS*DM;

    for (int i=0;i<NLAYERS;i++){
        const float* wq = Wq + (size_t)i*DM*DM;  const float* vbq = bq + i*DM;
        const float* wk = Wk + (size_t)i*DM*DM;  const float* vbk = bk + i*DM;
        const float* wv = Wv + (size_t)i*DM*DM;  const float* vbv = bv + i*DM;
        const float* wo = Wo + (size_t)i*DM*DM;  const float* vbo = bo + i*DM;
        const float* w1 = W1 + (size_t)i*DM*DFF; const float* vb1 = b1 + i*DFF;
        const float* w2 = W2 + (size_t)i*DFF*DM; const float* vb2 = b2 + i*DM;

        qkv_kernel<<<gQKV, 256>>>(x, wq, vbq, wk, vbk, wv, vbv, q, k, v);

        chunk_kv_kernel<<<gA, 1024>>>(k, v);
        attn_kernel<<<gA, 128>>>(q, k, v, a);

        // Wo: split-K=2 raw partials, then fused residual+reduce+LN -> x
        sgemm_kernel<4><<<gWo, 256>>>(DM, DM, DM/2, a, wo, nullptr, nullptr, part, PS);
        ln_red_kernel<<<NROWS, 256>>>(2, part, PS, x, vbo, ln1w + i*DM, ln1b + i*DM, x);

        // FFN
        sgemm_kernel<2><<<gFF, 256>>>(DM, DFF, DM, x, w1, vb1, nullptr, h, 0);
        sgemm_kernel<4><<<gW2, 256>>>(DFF, DM, DFF/4, h, w2, nullptr, nullptr, part, PS);
        ln_red_kernel<<<NROWS, 256>>>(4, part, PS, x, vb2, ln2w + i*DM, ln2b + i*DM, x);
    }

    head_kernel<<<BATCH*SFUT, 256>>>(x, mW, mb, sW, sb, (float*)d_out);
}

// round 4
// speedup vs baseline: 1.8091x; 1.0441x over previous
#include <cuda_runtime.h>
#include <math.h>

#define BATCH 4
#define SPAST 1024
#define SFUT 512
#define NTOK 1536
#define DM 256
#define NH 8
#define DH 32
#define DFF 2048
#define NLAYERS 8
#define NROWS (BATCH*NTOK)        // 6144
#define CHUNK 128
#define NCHUNK (NTOK/CHUNK)       // 12
#define NBH (BATCH*NH)            // 32

typedef unsigned long long ull;

// ---------------- scratch (no allocation allowed) ----------------
__device__ float g_x  [NROWS*DM];
__device__ float g_qb [NROWS*DM];
__device__ float g_kb [NROWS*DM];
__device__ float g_vb [NROWS*DM];
__device__ float g_ab [NROWS*DM];
__device__ float g_hb [NROWS*DFF];
__device__ float g_part[4*NROWS*DM];
__device__ float g_Sloc[NBH*NCHUNK*DH*DH];
__device__ float g_kloc[NBH*NCHUNK*DH];

// ---------------- packed fp32x2 helpers (sm_103a) ----------------
__device__ __forceinline__ ull pack2(float v){
    ull r; unsigned int u = __float_as_uint(v);
    asm("mov.b64 %0, {%1, %1};" : "=l"(r) : "r"(u));
    return r;
}
__device__ __forceinline__ void fma2(ull &d, ull a, ull b){
    asm("fma.rn.f32x2 %0, %1, %2, %0;" : "+l"(d) : "l"(a), "l"(b));
}
__device__ __forceinline__ float2 unp2(ull v){
    unsigned int lo, hi;
    asm("mov.b64 {%0, %1}, %2;" : "=r"(lo), "=r"(hi) : "l"(v));
    return make_float2(__uint_as_float(lo), __uint_as_float(hi));
}
__device__ __forceinline__ void cp_async16(void* dst, const void* src){
    unsigned int sdst = (unsigned int)__cvta_generic_to_shared(dst);
    asm volatile("cp.async.cg.shared.global [%0], [%1], 16;" :: "r"(sdst), "l"(src));
}
__device__ __forceinline__ void cp_commit(){ asm volatile("cp.async.commit_group;"); }
__device__ __forceinline__ void cp_wait0(){ asm volatile("cp.async.wait_group 0;"); }

// ---------------- embedding ----------------
__global__ void embed_kernel(const float* __restrict__ px, const float* __restrict__ py,
                             const float* __restrict__ fx,
                             const float* __restrict__ W, const float* __restrict__ b,
                             float* __restrict__ x)
{
    __shared__ float s[24];
    int r = blockIdx.x;
    int bb = r / NTOK, n = r % NTOK;
    int t = threadIdx.x;
    if (t < 24) {
        float v;
        if (t < 16) {
            v = (n < SPAST) ? px[(bb*SPAST+n)*16+t] : fx[(bb*SFUT+(n-SPAST))*16+t];
        } else {
            int yn = (n < SPAST) ? n : (SPAST-1);
            v = py[(bb*SPAST+yn)*8 + (t-16)];
        }
        s[t] = v;
    }
    __syncthreads();
    float acc = b[t];
    #pragma unroll
    for (int kk=0; kk<24; kk++) acc = fmaf(s[kk], W[kk*DM+t], acc);
    x[(size_t)r*DM + t] = acc;
}

// ---------------- GEMM core: cp.async double-buffered, packed fp32x2 ----------------
// EPI: 0 = +bias, 1 = elu(x+bias)+1, 2 = relu(x+bias), 4 = raw (no bias)
#define GBM 128
#define GBN 64
#define GBK 16

template<int EPI>
__device__ __forceinline__ void gemm_body(
    int K, int N, int kbeg, int kend,
    const float* __restrict__ A, const float* __restrict__ B,
    const float* __restrict__ bias, const float* __restrict__ res,
    float* __restrict__ C)
{
    __shared__ float As[2][GBK][GBM+2];   // A transposed, +2 pad
    __shared__ float Bs[2][GBK][GBN];
    const int t  = threadIdx.x;
    const int tx = t & 15;             // N direction
    const int ty = t >> 4;             // M direction
    const int bm = blockIdx.y * GBM;
    const int bn = blockIdx.x * GBN;

    ull acc[4][4];
    #pragma unroll
    for (int p=0;p<4;p++)
        #pragma unroll
        for (int j=0;j<4;j++) acc[p][j] = 0ull;

    const int arow0 = t >> 2;          // 0..63
    const int akq   = (t & 3) * 4;     // k offset 0,4,8,12
    const int brow  = t >> 4;          // 0..15
    const int bcol  = (t & 15) * 4;

    const float* Ap0 = A + (size_t)(bm+arow0)*K    + kbeg + akq;
    const float* Ap1 = A + (size_t)(bm+arow0+64)*K + kbeg + akq;
    const float* Bp  = B + (size_t)(kbeg+brow)*N   + bn + bcol;

    // prologue: tile 0
    {
        float4 a0 = *(const float4*)Ap0;
        float4 a1 = *(const float4*)Ap1;
        As[0][akq+0][arow0]=a0.x; As[0][akq+1][arow0]=a0.y; As[0][akq+2][arow0]=a0.z; As[0][akq+3][arow0]=a0.w;
        As[0][akq+0][arow0+64]=a1.x; As[0][akq+1][arow0+64]=a1.y; As[0][akq+2][arow0+64]=a1.z; As[0][akq+3][arow0+64]=a1.w;
        cp_async16(&Bs[0][brow][bcol], Bp);
        cp_commit();
        cp_wait0();
    }
    __syncthreads();

    const int nk = (kend - kbeg) / GBK;
    for (int kt=0; kt<nk; kt++){
        const int buf = kt & 1;
        const bool more = (kt+1 < nk);
        float4 na0, na1;
        if (more){
            cp_async16(&Bs[buf^1][brow][bcol], Bp + (size_t)(kt+1)*GBK*N);
            cp_commit();
            na0 = *(const float4*)(Ap0 + (kt+1)*GBK);
            na1 = *(const float4*)(Ap1 + (kt+1)*GBK);
        }
        #pragma unroll
        for (int kk=0;kk<GBK;kk++){
            const ull* arow = (const ull*)&As[buf][kk][0];
            ull a2[4];
            #pragma unroll
            for (int p=0;p<4;p++) a2[p] = arow[ty*4+p];
            ull bb2[4];
            #pragma unroll
            for (int j=0;j<4;j++) bb2[j] = pack2(Bs[buf][kk][tx*4+j]);
            #pragma unroll
            for (int p=0;p<4;p++)
                #pragma unroll
                for (int j=0;j<4;j++) fma2(acc[p][j], a2[p], bb2[j]);
        }
        if (more){
            const int nb = buf ^ 1;
            As[nb][akq+0][arow0]=na0.x; As[nb][akq+1][arow0]=na0.y; As[nb][akq+2][arow0]=na0.z; As[nb][akq+3][arow0]=na0.w;
            As[nb][akq+0][arow0+64]=na1.x; As[nb][akq+1][arow0+64]=na1.y; As[nb][akq+2][arow0+64]=na1.z; As[nb][akq+3][arow0+64]=na1.w;
            cp_wait0();
        }
        __syncthreads();
    }

    #pragma unroll
    for (int p=0;p<4;p++){
        float2 u[4];
        #pragma unroll
        for (int j=0;j<4;j++) u[j] = unp2(acc[p][j]);
        #pragma unroll
        for (int half=0; half<2; half++){
            int row = bm + ty*8 + 2*p + half;
            float cv[4];
            #pragma unroll
            for (int j=0;j<4;j++){
                float vv = (half==0)? u[j].x : u[j].y;
                int col = bn + tx*4 + j;
                if (EPI != 4) vv += bias[col];
                if (EPI == 1) vv = (vv>=0.f)? vv+1.f : expf(vv);   // elu(x)+1
                if (EPI == 2) vv = fmaxf(vv, 0.f);
                cv[j]=vv;
            }
            float4 o; o.x=cv[0]; o.y=cv[1]; o.z=cv[2]; o.w=cv[3];
            *(float4*)(C + (size_t)row*N + bn + tx*4) = o;
        }
    }
}

// plain GEMM, optional split-K via blockIdx.z writing partial buffers
template<int EPI>
__global__ void __launch_bounds__(256) sgemm_kernel(
    int K, int N, int ksplit,
    const float* __restrict__ A, const float* __restrict__ B,
    const float* __restrict__ bias, const float* __restrict__ res,
    float* __restrict__ C, size_t cstride)
{
    int z = blockIdx.z;
    gemm_body<EPI>(K, N, z*ksplit, (z+1)*ksplit, A, B, bias, res, C + (size_t)z*cstride);
}

// fused Q/K/V: z selects weight/bias/output and epilogue
__global__ void __launch_bounds__(256) qkv_kernel(
    const float* __restrict__ x,
    const float* __restrict__ Wq, const float* __restrict__ bq,
    const float* __restrict__ Wk, const float* __restrict__ bk,
    const float* __restrict__ Wv, const float* __restrict__ bv,
    float* __restrict__ q, float* __restrict__ k, float* __restrict__ v)
{
    int z = blockIdx.z;
    if (z == 0)      gemm_body<1>(DM, DM, 0, DM, x, Wq, bq, nullptr, q);
    else if (z == 1) gemm_body<1>(DM, DM, 0, DM, x, Wk, bk, nullptr, k);
    else             gemm_body<0>(DM, DM, 0, DM, x, Wv, bv, nullptr, v);
}

// ---------------- per-chunk K^T V state + K column sums ----------------
__global__ void __launch_bounds__(1024) chunk_kv_kernel(const float* __restrict__ k,
                                                        const float* __restrict__ v)
{
    int c = blockIdx.x, bh = blockIdx.y;
    int b = bh >> 3, h = bh & 7;
    __shared__ float ks[CHUNK][DH];
    __shared__ float vs[CHUNK][DH];
    int t = threadIdx.x;
    int base = b*NTOK + c*CHUNK;
    for (int idx=t; idx<CHUNK*DH; idx+=1024){
        int row = idx >> 5, col = idx & 31;
        size_t g = (size_t)(base+row)*DM + h*DH + col;
        ks[row][col] = k[g];
        vs[row][col] = v[g];
    }
    __syncthreads();
    int d = t >> 5, m = t & 31;
    float s = 0.f;
    #pragma unroll 8
    for (int j=0;j<CHUNK;j++) s = fmaf(ks[j][d], vs[j][m], s);
    g_Sloc[((size_t)bh*NCHUNK + c)*DH*DH + d*DH + m] = s;
    if (t < DH){
        float kssum = 0.f;
        #pragma unroll 8
        for (int j=0;j<CHUNK;j++) kssum += ks[j][t];
        g_kloc[((size_t)bh*NCHUNK + c)*DH + t] = kssum;
    }
}

// ---------------- attention output (inline chunk-prefix; j-loop unrolled x2) ----------------
__global__ void __launch_bounds__(128) attn_kernel(const float* __restrict__ q,
                                                   const float* __restrict__ k,
                                                   const float* __restrict__ v,
                                                   float* __restrict__ a)
{
    int c = blockIdx.x, bh = blockIdx.y;
    int b = bh >> 3, h = bh & 7;
    __shared__ float ks[CHUNK][DH];
    __shared__ float vs[CHUNK][DH];
    __shared__ float Ss[DH][DH];
    __shared__ float kss[DH];
    int t = threadIdx.x;
    int base = b*NTOK + c*CHUNK;
    for (int idx=t; idx<CHUNK*DH; idx+=128){
        int row = idx >> 5, col = idx & 31;
        size_t g = (size_t)(base+row)*DM + h*DH + col;
        ks[row][col] = k[g];
        vs[row][col] = v[g];
    }
    // exclusive prefix of chunk states, computed inline (c <= 11 chunks, L2-resident)
    for (int idx=t; idx<DH*DH; idx+=128){
        float s = 0.f;
        const float* p = g_Sloc + (size_t)bh*NCHUNK*DH*DH + idx;
        for (int cc=0; cc<c; cc++) s += p[cc*DH*DH];
        Ss[idx>>5][idx&31] = s;
    }
    if (t < DH){
        float s = 0.f;
        const float* p = g_kloc + (size_t)bh*NCHUNK*DH + t;
        for (int cc=0; cc<c; cc++) s += p[cc*DH];
        kss[t] = s;
    }
    __syncthreads();

    float qr[DH], num[DH];
    {
        const float4* qp = (const float4*)(q + (size_t)(base+t)*DM + h*DH);
        #pragma unroll
        for (int d4=0; d4<8; d4++){
            float4 w4 = qp[d4];
            qr[4*d4+0]=w4.x; qr[4*d4+1]=w4.y; qr[4*d4+2]=w4.z; qr[4*d4+3]=w4.w;
        }
    }
    #pragma unroll
    for (int m=0;m<DH;m++) num[m] = 0.f;
    float z = 0.f;

    #pragma unroll
    for (int d=0; d<DH; d++){
        float qa = qr[d];
        z = fmaf(qa, kss[d], z);
        #pragma unroll
        for (int m=0;m<DH;m++) num[m] = fmaf(qa, Ss[d][m], num[m]);
    }
    // intra-chunk causal; trip count = (t|31)+1, multiple of 2 -> unroll by 2,
    // two independent aa chains for ILP at low occupancy
    int jend = t | 31;
    for (int j=0; j<=jend; j+=2){
        float aa0 = 0.f, aa1 = 0.f;
        #pragma unroll
        for (int d=0; d<DH; d++){
            aa0 = fmaf(qr[d], ks[j  ][d], aa0);
            aa1 = fmaf(qr[d], ks[j+1][d], aa1);
        }
        aa0 = (j   <= t) ? aa0 : 0.f;
        aa1 = (j+1 <= t) ? aa1 : 0.f;
        z += aa0 + aa1;
        #pragma unroll
        for (int m=0;m<DH;m++){
            float nm = fmaf(aa0, vs[j][m], num[m]);
            num[m] = fmaf(aa1, vs[j+1][m], nm);
        }
    }
    float inv = 1.f / (z + 1e-6f);
    float4* op = (float4*)(a + (size_t)(base+t)*DM + h*DH);
    #pragma unroll
    for (int d4=0; d4<8; d4++)
        op[d4] = make_float4(num[4*d4]*inv, num[4*d4+1]*inv, num[4*d4+2]*inv, num[4*d4+3]*inv);
}

// ---------------- residual + split-K reduce + LayerNorm (fused) ----------------
__global__ void __launch_bounds__(256) ln_red_kernel(
    int np, const float* __restrict__ part, size_t pstride,
    const float* __restrict__ xin, const float* __restrict__ bias,
    const float* __restrict__ w, const float* __restrict__ b,
    float* __restrict__ out)
{
    __shared__ float red[8], red2[8];
    int r = blockIdx.x, t = threadIdx.x;
    size_t o = (size_t)r*DM + t;
    float v = xin[o] + bias[t];
    for (int i=0;i<np;i++) v += part[(size_t)i*pstride + o];
    float s = v, s2 = v*v;
    #pragma unroll
    for (int off=16;off;off>>=1){ s += __shfl_xor_sync(~0u,s,off); s2 += __shfl_xor_sync(~0u,s2,off); }
    int warp = t >> 5, lane = t & 31;
    if (lane == 0){ red[warp] = s; red2[warp] = s2; }
    __syncthreads();
    float S=0.f, S2=0.f;
    #pragma unroll
    for (int i=0;i<8;i++){ S += red[i]; S2 += red2[i]; }
    float mean = S * (1.f/DM);
    float var  = S2 * (1.f/DM) - mean*mean;
    out[o] = (v - mean) * rsqrtf(var + 1e-5f) * w[t] + b[t];
}

// ---------------- head: mean / sigma ----------------
__global__ void __launch_bounds__(256) head_kernel(const float* __restrict__ x,
                                                   const float* __restrict__ mW, const float* __restrict__ mb,
                                                   const float* __restrict__ sW, const float* __restrict__ sb,
                                                   float* __restrict__ out)
{
    __shared__ float sx[DM];
    int r = blockIdx.x;
    int b = r / SFUT, s = r % SFUT;
    const float* xr = x + (size_t)(b*NTOK + SPAST + s)*DM;
    int t = threadIdx.x;
    sx[t] = xr[t];
    __syncthreads();
    int warp = t >> 5, lane = t & 31;
    float am = 0.f, as = 0.f;
    for (int kk=lane; kk<DM; kk+=32){
        float xv = sx[kk];
        am = fmaf(xv, mW[kk*8 + warp], am);
        as = fmaf(xv, sW[kk*8 + warp], as);
    }
    #pragma unroll
    for (int off=16;off;off>>=1){ am += __shfl_xor_sync(~0u,am,off); as += __shfl_xor_sync(~0u,as,off); }
    if (lane == 0){
        int o = r*8 + warp;
        out[o] = am + mb[warp];
        float sp = as + sb[warp];
        float spv = (sp > 20.f) ? sp : log1pf(expf(sp));
        out[BATCH*SFUT*8 + o] = 0.01f + 0.99f*spv;
    }
}

// ---------------- launch ----------------
extern "C" void kernel_launch(void* const* d_in, const int* in_sizes, int n_in,
                              void* d_out, int out_size)
{
    (void)in_sizes; (void)n_in; (void)out_size;
    const float* past_x   = (const float*)d_in[0];
    const float* past_y   = (const float*)d_in[1];
    const float* future_x = (const float*)d_in[2];
    const float* enc_W    = (const float*)d_in[3];
    const float* enc_b    = (const float*)d_in[4];
    const float* Wq  = (const float*)d_in[5];  const float* bq  = (const float*)d_in[6];
    const float* Wk  = (const float*)d_in[7];  const float* bk  = (const float*)d_in[8];
    const float* Wv  = (const float*)d_in[9];  const float* bv  = (const float*)d_in[10];
    const float* Wo  = (const float*)d_in[11]; const float* bo  = (const float*)d_in[12];
    const float* ln1w= (const float*)d_in[13]; const float* ln1b= (const float*)d_in[14];
    const float* W1  = (const float*)d_in[15]; const float* b1  = (const float*)d_in[16];
    const float* W2  = (const float*)d_in[17]; const float* b2  = (const float*)d_in[18];
    const float* ln2w= (const float*)d_in[19]; const float* ln2b= (const float*)d_in[20];
    const float* mW  = (const float*)d_in[21]; const float* mb  = (const float*)d_in[22];
    const float* sW  = (const float*)d_in[23]; const float* sb  = (const float*)d_in[24];

    float *x,*q,*k,*v,*a,*h,*part;
    cudaGetSymbolAddress((void**)&x,   g_x);
    cudaGetSymbolAddress((void**)&q,   g_qb);
    cudaGetSymbolAddress((void**)&k,   g_kb);
    cudaGetSymbolAddress((void**)&v,   g_vb);
    cudaGetSymbolAddress((void**)&a,   g_ab);
    cudaGetSymbolAddress((void**)&h,   g_hb);
    cudaGetSymbolAddress((void**)&part,g_part);

    embed_kernel<<<NROWS, 256>>>(past_x, past_y, future_x, enc_W, enc_b, x);

    dim3 gQKV(DM/GBN,  NROWS/GBM, 3);   // 576 blocks
    dim3 gWo (DM/GBN,  NROWS/GBM, 2);   // split-K 2 -> 384 blocks
    dim3 gFF (DFF/GBN, NROWS/GBM, 1);   // 1536 blocks
    dim3 gW2 (DM/GBN,  NROWS/GBM, 4);   // split-K 4 -> 768 blocks
    dim3 gA  (NCHUNK, NBH);

    const size_t PS = (size_t)NROWS*DM;

    for (int i=0;i<NLAYERS;i++){
        const float* wq = Wq + (size_t)i*DM*DM;  const float* vbq = bq + i*DM;
        const float* wk = Wk + (size_t)i*DM*DM;  const float* vbk = bk + i*DM;
        const float* wv = Wv + (size_t)i*DM*DM;  const float* vbv = bv + i*DM;
        const float* wo = Wo + (size_t)i*DM*DM;  const float* vbo = bo + i*DM;
        const float* w1 = W1 + (size_t)i*DM*DFF; const float* vb1 = b1 + i*DFF;
        const float* w2 = W2 + (size_t)i*DFF*DM; const float* vb2 = b2 + i*DM;

        qkv_kernel<<<gQKV, 256>>>(x, wq, vbq, wk, vbk, wv, vbv, q, k, v);

        chunk_kv_kernel<<<gA, 1024>>>(k, v);
        attn_kernel<<<gA, 128>>>(q, k, v, a);

        // Wo: split-K=2 raw partials, then fused residual+reduce+LN -> x
        sgemm_kernel<4><<<gWo, 256>>>(DM, DM, DM/2, a, wo, nullptr, nullptr, part, PS);
        ln_red_kernel<<<NROWS, 256>>>(2, part, PS, x, vbo, ln1w + i*DM, ln1b + i*DM, x);

        // FFN
        sgemm_kernel<2><<<gFF, 256>>>(DM, DFF, DM, x, w1, vb1, nullptr, h, 0);
        sgemm_kernel<4><<<gW2, 256>>>(DFF, DM, DFF/4, h, w2, nullptr, nullptr, part, PS);
        ln_red_kernel<<<NROWS, 256>>>(4, part, PS, x, vb2, ln2w + i*DM, ln2b + i*DM, x);
    }

    head_kernel<<<BATCH*SFUT, 256>>>(x, mW, mb, sW, sb, (float*)d_out);
}

// round 6
// speedup vs baseline: 2.6895x; 1.4866x over previous
#include <cuda_runtime.h>
#include <cuda_bf16.h>
#include <math.h>

#define BATCH 4
#define SPAST 1024
#define SFUT 512
#define NTOK 1536
#define DM 256
#define NH 8
#define DH 32
#define DFF 2048
#define NLAYERS 8
#define NROWS (BATCH*NTOK)        // 6144
#define CHUNK 128
#define NCHUNK (NTOK/CHUNK)       // 12
#define NBH (BATCH*NH)            // 32

typedef unsigned long long ull;
typedef __nv_bfloat16 bf16;
typedef __nv_bfloat162 bf162;

// ---------------- scratch (no allocation allowed) ----------------
__device__ float g_x  [NROWS*DM];
__device__ float g_qb [NROWS*DM];
__device__ float g_kb [NROWS*DM];
__device__ float g_vb [NROWS*DM];
__device__ float g_part[4*NROWS*DM];
__device__ float g_Sloc[NBH*NCHUNK*DH*DH];
__device__ float g_kloc[NBH*NCHUNK*DH];

__device__ bf16 g_xh[NROWS*DM],  g_xl[NROWS*DM];
__device__ bf16 g_ah[NROWS*DM],  g_al[NROWS*DM];
__device__ bf16 g_hh[NROWS*DFF], g_hl[NROWS*DFF];
// transposed K-major weights, hi/lo split: [L][N][K]
__device__ bf16 g_wqh[NLAYERS*DM*DM],  g_wql[NLAYERS*DM*DM];
__device__ bf16 g_wkh[NLAYERS*DM*DM],  g_wkl[NLAYERS*DM*DM];
__device__ bf16 g_wvh[NLAYERS*DM*DM],  g_wvl[NLAYERS*DM*DM];
__device__ bf16 g_woh[NLAYERS*DM*DM],  g_wol[NLAYERS*DM*DM];
__device__ bf16 g_w1h[NLAYERS*DM*DFF], g_w1l[NLAYERS*DM*DFF];
__device__ bf16 g_w2h[NLAYERS*DFF*DM], g_w2l[NLAYERS*DFF*DM];

// ---------------- helpers ----------------
__device__ __forceinline__ void cp_async16(void* dst, const void* src){
    unsigned int sdst = (unsigned int)__cvta_generic_to_shared(dst);
    asm volatile("cp.async.cg.shared.global [%0], [%1], 16;" :: "r"(sdst), "l"(src));
}
__device__ __forceinline__ void cp_commit(){ asm volatile("cp.async.commit_group;"); }
__device__ __forceinline__ void cp_wait0(){ asm volatile("cp.async.wait_group 0;"); }

__device__ __forceinline__ unsigned smem_u32(const void* p){
    return (unsigned)__cvta_generic_to_shared(p);
}
__device__ __forceinline__ void ldsm_x4(unsigned* r, unsigned addr){
    asm volatile("ldmatrix.sync.aligned.m8n8.x4.shared.b16 {%0,%1,%2,%3}, [%4];"
        : "=r"(r[0]), "=r"(r[1]), "=r"(r[2]), "=r"(r[3]) : "r"(addr));
}
__device__ __forceinline__ void ldsm_x2(unsigned* r, unsigned addr){
    asm volatile("ldmatrix.sync.aligned.m8n8.x2.shared.b16 {%0,%1}, [%2];"
        : "=r"(r[0]), "=r"(r[1]) : "r"(addr));
}
__device__ __forceinline__ void mma16816(float* c, const unsigned* a, const unsigned* b){
    asm volatile("mma.sync.aligned.m16n8k16.row.col.f32.bf16.bf16.f32 "
        "{%0,%1,%2,%3}, {%4,%5,%6,%7}, {%8,%9}, {%0,%1,%2,%3};"
        : "+f"(c[0]), "+f"(c[1]), "+f"(c[2]), "+f"(c[3])
        : "r"(a[0]), "r"(a[1]), "r"(a[2]), "r"(a[3]), "r"(b[0]), "r"(b[1]));
}
__device__ __forceinline__ void split_bf16(float v, bf16& h, bf16& l){
    h = __float2bfloat16(v);
    l = __float2bfloat16(v - __bfloat162float(h));
}

// ---------------- weight transpose + bf16 split: W[L][K][N] -> Wt[L][N][K] hi/lo ----------------
__global__ void convw_kernel(const float* __restrict__ W, bf16* __restrict__ Oh, bf16* __restrict__ Ol,
                             int K, int N)
{
    __shared__ float s[32][33];
    int l = blockIdx.z;
    const float* Wp = W + (size_t)l*K*N;
    bf16* OhP = Oh + (size_t)l*K*N;
    bf16* OlP = Ol + (size_t)l*K*N;
    int n0 = blockIdx.x*32, k0 = blockIdx.y*32;
    int tx = threadIdx.x, ty = threadIdx.y;
    #pragma unroll
    for (int i=0;i<4;i++)
        s[ty+8*i][tx] = Wp[(size_t)(k0+ty+8*i)*N + n0+tx];
    __syncthreads();
    #pragma unroll
    for (int i=0;i<4;i++){
        float v = s[tx][ty+8*i];
        bf16 h, lo; split_bf16(v, h, lo);
        size_t o = (size_t)(n0+ty+8*i)*K + k0+tx;
        OhP[o] = h; OlP[o] = lo;
    }
}

// ---------------- embedding (fp32 + bf16 split out) ----------------
__global__ void embed_kernel(const float* __restrict__ px, const float* __restrict__ py,
                             const float* __restrict__ fx,
                             const float* __restrict__ W, const float* __restrict__ b,
                             float* __restrict__ x, bf16* __restrict__ xh, bf16* __restrict__ xl)
{
    __shared__ float s[24];
    int r = blockIdx.x;
    int bb = r / NTOK, n = r % NTOK;
    int t = threadIdx.x;
    if (t < 24) {
        float v;
        if (t < 16) {
            v = (n < SPAST) ? px[(bb*SPAST+n)*16+t] : fx[(bb*SFUT+(n-SPAST))*16+t];
        } else {
            int yn = (n < SPAST) ? n : (SPAST-1);
            v = py[(bb*SPAST+yn)*8 + (t-16)];
        }
        s[t] = v;
    }
    __syncthreads();
    float acc = b[t];
    #pragma unroll
    for (int kk=0; kk<24; kk++) acc = fmaf(s[kk], W[kk*DM+t], acc);
    size_t o = (size_t)r*DM + t;
    x[o] = acc;
    bf16 h, lo; split_bf16(acc, h, lo);
    xh[o] = h; xl[o] = lo;
}

// ---------------- bf16 error-split tensor-core GEMM (mma.sync, sm_80+ ISA) ----------------
// Block tile 128x64, BK=32. 256 threads = 8 warps in 4(M) x 2(N), each warp 32x32.
// D = Ah*Bh^T + Ah*Bl^T + Al*Bh^T  (fp32 accum)
// EPI: 0 = +bias fp32 out, 1 = elu(x+bias)+1 fp32 out, 2 = relu(x+bias)->bf16 h/l out, 4 = raw fp32 out
#define BM 128
#define BN 64
#define BK 32
#define SAPAD 40   // BK + 8 pad (80B row stride: conflict-free ldmatrix)

template<int EPI>
__device__ void gemm_core(int K, int Ntot, int kbeg, int kend,
    const bf16* __restrict__ Ah, const bf16* __restrict__ Al,
    const bf16* __restrict__ Bh, const bf16* __restrict__ Bl,
    const float* __restrict__ bias,
    float* __restrict__ Cf, bf16* __restrict__ Ch, bf16* __restrict__ Cl)
{
    __shared__ bf16 sAh[BM][SAPAD], sAl[BM][SAPAD];
    __shared__ bf16 sBh[BN][SAPAD], sBl[BN][SAPAD];

    const int t = threadIdx.x;
    const int lane = t & 31, warp = t >> 5;
    const int wm = warp & 3;            // 0..3 : M block of 32
    const int wn = warp >> 2;           // 0..1 : N block of 32
    const int bm = blockIdx.y * BM;
    const int bn = blockIdx.x * BN;

    float acc[2][4][4];
    #pragma unroll
    for (int mt=0;mt<2;mt++)
        #pragma unroll
        for (int nt=0;nt<4;nt++)
            #pragma unroll
            for (int u=0;u<4;u++) acc[mt][nt][u] = 0.f;

    // load indexing
    const int ar0 = t >> 1;              // unused style; use idx loop below
    (void)ar0;

    for (int k0=kbeg; k0<kend; k0+=BK){
        // A: 128 rows x 32 k = 512 uint4 (x2 for h/l); 2 per thread each
        #pragma unroll
        for (int i=0;i<2;i++){
            int idx = t + i*256;
            int row = idx >> 2, kp = idx & 3;
            size_t go = (size_t)(bm+row)*K + k0 + kp*8;
            cp_async16(&sAh[row][kp*8], Ah + go);
            cp_async16(&sAl[row][kp*8], Al + go);
        }
        // B: 64 rows x 32 k = 256 uint4 each; 1 per thread
        {
            int row = t >> 2, kp = t & 3;
            size_t go = (size_t)(bn+row)*K + k0 + kp*8;
            cp_async16(&sBh[row][kp*8], Bh + go);
            cp_async16(&sBl[row][kp*8], Bl + go);
        }
        cp_commit(); cp_wait0();
        __syncthreads();

        #pragma unroll
        for (int ks=0; ks<2; ks++){
            unsigned ah[2][4], al[2][4], bh[4][2], bl[4][2];
            #pragma unroll
            for (int mt=0;mt<2;mt++){
                int row = wm*32 + mt*16 + (lane & 15);
                int kc  = ks*16 + (lane >> 4)*8;
                ldsm_x4(ah[mt], smem_u32(&sAh[row][kc]));
                ldsm_x4(al[mt], smem_u32(&sAl[row][kc]));
            }
            #pragma unroll
            for (int nt=0;nt<4;nt++){
                int row = wn*32 + nt*8 + (lane & 7);
                int kc  = ks*16 + ((lane >> 3) & 1)*8;
                ldsm_x2(bh[nt], smem_u32(&sBh[row][kc]));
                ldsm_x2(bl[nt], smem_u32(&sBl[row][kc]));
            }
            #pragma unroll
            for (int mt=0;mt<2;mt++)
                #pragma unroll
                for (int nt=0;nt<4;nt++){
                    mma16816(acc[mt][nt], ah[mt], bh[nt]);
                    mma16816(acc[mt][nt], ah[mt], bl[nt]);
                    mma16816(acc[mt][nt], al[mt], bh[nt]);
                }
        }
        __syncthreads();
    }

    // ---- epilogue ----
    #pragma unroll
    for (int mt=0;mt<2;mt++){
        #pragma unroll
        for (int nt=0;nt<4;nt++){
            int col = bn + wn*32 + nt*8 + (lane & 3)*2;
            #pragma unroll
            for (int half=0; half<2; half++){
                int row = bm + wm*32 + mt*16 + (lane >> 2) + half*8;
                float v0 = acc[mt][nt][half*2+0];
                float v1 = acc[mt][nt][half*2+1];
                if (EPI != 4){ v0 += bias[col]; v1 += bias[col+1]; }
                if (EPI == 1){
                    v0 = (v0>=0.f)? v0+1.f : expf(v0);
                    v1 = (v1>=0.f)? v1+1.f : expf(v1);
                }
                if (EPI == 2){
                    v0 = fmaxf(v0, 0.f); v1 = fmaxf(v1, 0.f);
                    bf16 h0,l0,h1,l1; split_bf16(v0,h0,l0); split_bf16(v1,h1,l1);
                    bf162 ph; ph.x=h0; ph.y=h1;
                    bf162 pl; pl.x=l0; pl.y=l1;
                    size_t o = (size_t)row*Ntot + col;
                    *(bf162*)(Ch + o) = ph;
                    *(bf162*)(Cl + o) = pl;
                } else {
                    float2 o2; o2.x=v0; o2.y=v1;
                    *(float2*)(Cf + (size_t)row*Ntot + col) = o2;
                }
            }
        }
    }
}

template<int EPI>
__global__ void __launch_bounds__(256) bgemm_kernel(
    int K, int Ntot, int ksplit,
    const bf16* __restrict__ Ah, const bf16* __restrict__ Al,
    const bf16* __restrict__ Bh, const bf16* __restrict__ Bl,
    const float* __restrict__ bias,
    float* __restrict__ Cf, bf16* __restrict__ Ch, bf16* __restrict__ Cl, size_t cstride)
{
    int z = blockIdx.z;
    gemm_core<EPI>(K, Ntot, z*ksplit, (z+1)*ksplit, Ah, Al, Bh, Bl, bias,
                   Cf + (size_t)z*cstride, Ch, Cl);
}

__global__ void __launch_bounds__(256) qkv_bgemm(
    const bf16* __restrict__ xh, const bf16* __restrict__ xl,
    const bf16* __restrict__ wqh, const bf16* __restrict__ wql, const float* __restrict__ bq,
    const bf16* __restrict__ wkh, const bf16* __restrict__ wkl, const float* __restrict__ bk,
    const bf16* __restrict__ wvh, const bf16* __restrict__ wvl, const float* __restrict__ bv,
    float* __restrict__ q, float* __restrict__ k, float* __restrict__ v)
{
    int z = blockIdx.z;
    if (z == 0)      gemm_core<1>(DM, DM, 0, DM, xh, xl, wqh, wql, bq, q, nullptr, nullptr);
    else if (z == 1) gemm_core<1>(DM, DM, 0, DM, xh, xl, wkh, wkl, bk, k, nullptr, nullptr);
    else             gemm_core<0>(DM, DM, 0, DM, xh, xl, wvh, wvl, bv, v, nullptr, nullptr);
}

// ---------------- per-chunk K^T V state + K column sums ----------------
__global__ void __launch_bounds__(1024) chunk_kv_kernel(const float* __restrict__ k,
                                                        const float* __restrict__ v)
{
    int c = blockIdx.x, bh = blockIdx.y;
    int b = bh >> 3, h = bh & 7;
    __shared__ float ks[CHUNK][DH];
    __shared__ float vs[CHUNK][DH];
    int t = threadIdx.x;
    int base = b*NTOK + c*CHUNK;
    for (int idx=t; idx<CHUNK*DH; idx+=1024){
        int row = idx >> 5, col = idx & 31;
        size_t g = (size_t)(base+row)*DM + h*DH + col;
        ks[row][col] = k[g];
        vs[row][col] = v[g];
    }
    __syncthreads();
    int d = t >> 5, m = t & 31;
    float s = 0.f;
    #pragma unroll 8
    for (int j=0;j<CHUNK;j++) s = fmaf(ks[j][d], vs[j][m], s);
    g_Sloc[((size_t)bh*NCHUNK + c)*DH*DH + d*DH + m] = s;
    if (t < DH){
        float kssum = 0.f;
        #pragma unroll 8
        for (int j=0;j<CHUNK;j++) kssum += ks[j][t];
        g_kloc[((size_t)bh*NCHUNK + c)*DH + t] = kssum;
    }
}

// ---------------- attention output (fp32 math, bf16 hi/lo split out) ----------------
__global__ void __launch_bounds__(128) attn_kernel(const float* __restrict__ q,
                                                   const float* __restrict__ k,
                                                   const float* __restrict__ v,
                                                   bf16* __restrict__ ah_out,
                                                   bf16* __restrict__ al_out)
{
    int c = blockIdx.x, bh = blockIdx.y;
    int b = bh >> 3, h = bh & 7;
    __shared__ float ks[CHUNK][DH];
    __shared__ float vs[CHUNK][DH];
    __shared__ float Ss[DH][DH];
    __shared__ float kss[DH];
    int t = threadIdx.x;
    int base = b*NTOK + c*CHUNK;
    for (int idx=t; idx<CHUNK*DH; idx+=128){
        int row = idx >> 5, col = idx & 31;
        size_t g = (size_t)(base+row)*DM + h*DH + col;
        ks[row][col] = k[g];
        vs[row][col] = v[g];
    }
    for (int idx=t; idx<DH*DH; idx+=128){
        float s = 0.f;
        const float* p = g_Sloc + (size_t)bh*NCHUNK*DH*DH + idx;
        for (int cc=0; cc<c; cc++) s += p[cc*DH*DH];
        Ss[idx>>5][idx&31] = s;
    }
    if (t < DH){
        float s = 0.f;
        const float* p = g_kloc + (size_t)bh*NCHUNK*DH + t;
        for (int cc=0; cc<c; cc++) s += p[cc*DH];
        kss[t] = s;
    }
    __syncthreads();

    float qr[DH], num[DH];
    {
        const float4* qp = (const float4*)(q + (size_t)(base+t)*DM + h*DH);
        #pragma unroll
        for (int d4=0; d4<8; d4++){
            float4 w4 = qp[d4];
            qr[4*d4+0]=w4.x; qr[4*d4+1]=w4.y; qr[4*d4+2]=w4.z; qr[4*d4+3]=w4.w;
        }
    }
    #pragma unroll
    for (int m=0;m<DH;m++) num[m] = 0.f;
    float z = 0.f;

    #pragma unroll
    for (int d=0; d<DH; d++){
        float qa = qr[d];
        z = fmaf(qa, kss[d], z);
        #pragma unroll
        for (int m=0;m<DH;m++) num[m] = fmaf(qa, Ss[d][m], num[m]);
    }
    int jend = t | 31;
    for (int j=0; j<=jend; j+=2){
        float aa0 = 0.f, aa1 = 0.f;
        #pragma unroll
        for (int d=0; d<DH; d++){
            aa0 = fmaf(qr[d], ks[j  ][d], aa0);
            aa1 = fmaf(qr[d], ks[j+1][d], aa1);
        }
        aa0 = (j   <= t) ? aa0 : 0.f;
        aa1 = (j+1 <= t) ? aa1 : 0.f;
        z += aa0 + aa1;
        #pragma unroll
        for (int m=0;m<DH;m++){
            float nm = fmaf(aa0, vs[j][m], num[m]);
            num[m] = fmaf(aa1, vs[j+1][m], nm);
        }
    }
    float inv = 1.f / (z + 1e-6f);
    size_t ob = (size_t)(base+t)*DM + h*DH;
    #pragma unroll
    for (int m=0;m<DH;m+=2){
        float v0 = num[m]*inv, v1 = num[m+1]*inv;
        bf16 h0,l0,h1,l1; split_bf16(v0,h0,l0); split_bf16(v1,h1,l1);
        bf162 ph; ph.x=h0; ph.y=h1;
        bf162 pl; pl.x=l0; pl.y=l1;
        *(bf162*)(ah_out + ob + m) = ph;
        *(bf162*)(al_out + ob + m) = pl;
    }
}

// ---------------- residual + split-K reduce + LayerNorm (fused, + bf16 split out) ----------------
__global__ void __launch_bounds__(256) ln_red_kernel(
    int np, const float* __restrict__ part, size_t pstride,
    const float* __restrict__ xin, const float* __restrict__ bias,
    const float* __restrict__ w, const float* __restrict__ b,
    float* __restrict__ out, bf16* __restrict__ oh, bf16* __restrict__ ol)
{
    __shared__ float red[8], red2[8];
    int r = blockIdx.x, t = threadIdx.x;
    size_t o = (size_t)r*DM + t;
    float v = xin[o] + bias[t];
    for (int i=0;i<np;i++) v += part[(size_t)i*pstride + o];
    float s = v, s2 = v*v;
    #pragma unroll
    for (int off=16;off;off>>=1){ s += __shfl_xor_sync(~0u,s,off); s2 += __shfl_xor_sync(~0u,s2,off); }
    int warp = t >> 5, lane = t & 31;
    if (lane == 0){ red[warp] = s; red2[warp] = s2; }
    __syncthreads();
    float S=0.f, S2=0.f;
    #pragma unroll
    for (int i=0;i<8;i++){ S += red[i]; S2 += red2[i]; }
    float mean = S * (1.f/DM);
    float var  = S2 * (1.f/DM) - mean*mean;
    float ov = (v - mean) * rsqrtf(var + 1e-5f) * w[t] + b[t];
    out[o] = ov;
    bf16 h, lo; split_bf16(ov, h, lo);
    oh[o] = h; ol[o] = lo;
}

// ---------------- head: mean / sigma ----------------
__global__ void __launch_bounds__(256) head_kernel(const float* __restrict__ x,
                                                   const float* __restrict__ mW, const float* __restrict__ mb,
                                                   const float* __restrict__ sW, const float* __restrict__ sb,
                                                   float* __restrict__ out)
{
    __shared__ float sx[DM];
    int r = blockIdx.x;
    int b = r / SFUT, s = r % SFUT;
    const float* xr = x + (size_t)(b*NTOK + SPAST + s)*DM;
    int t = threadIdx.x;
    sx[t] = xr[t];
    __syncthreads();
    int warp = t >> 5, lane = t & 31;
    float am = 0.f, as = 0.f;
    for (int kk=lane; kk<DM; kk+=32){
        float xv = sx[kk];
        am = fmaf(xv, mW[kk*8 + warp], am);
        as = fmaf(xv, sW[kk*8 + warp], as);
    }
    #pragma unroll
    for (int off=16;off;off>>=1){ am += __shfl_xor_sync(~0u,am,off); as += __shfl_xor_sync(~0u,as,off); }
    if (lane == 0){
        int o = r*8 + warp;
        out[o] = am + mb[warp];
        float sp = as + sb[warp];
        float spv = (sp > 20.f) ? sp : log1pf(expf(sp));
        out[BATCH*SFUT*8 + o] = 0.01f + 0.99f*spv;
    }
}

// ---------------- launch ----------------
extern "C" void kernel_launch(void* const* d_in, const int* in_sizes, int n_in,
                              void* d_out, int out_size)
{
    (void)in_sizes; (void)n_in; (void)out_size;
    const float* past_x   = (const float*)d_in[0];
    const float* past_y   = (const float*)d_in[1];
    const float* future_x = (const float*)d_in[2];
    const float* enc_W    = (const float*)d_in[3];
    const float* enc_b    = (const float*)d_in[4];
    const float* Wq  = (const float*)d_in[5];  const float* bq  = (const float*)d_in[6];
    const float* Wk  = (const float*)d_in[7];  const float* bk  = (const float*)d_in[8];
    const float* Wv  = (const float*)d_in[9];  const float* bv  = (const float*)d_in[10];
    const float* Wo  = (const float*)d_in[11]; const float* bo  = (const float*)d_in[12];
    const float* ln1w= (const float*)d_in[13]; const float* ln1b= (const float*)d_in[14];
    const float* W1  = (const float*)d_in[15]; const float* b1  = (const float*)d_in[16];
    const float* W2  = (const float*)d_in[17]; const float* b2  = (const float*)d_in[18];
    const float* ln2w= (const float*)d_in[19]; const float* ln2b= (const float*)d_in[20];
    const float* mW  = (const float*)d_in[21]; const float* mb  = (const float*)d_in[22];
    const float* sW  = (const float*)d_in[23]; const float* sb  = (const float*)d_in[24];

    float *x,*q,*k,*v,*part;
    bf16 *xh,*xl,*ah,*al,*hh,*hl;
    bf16 *wqh,*wql,*wkh,*wkl,*wvh,*wvl,*woh,*wol,*w1h,*w1l,*w2h,*w2l;
    cudaGetSymbolAddress((void**)&x,   g_x);
    cudaGetSymbolAddress((void**)&q,   g_qb);
    cudaGetSymbolAddress((void**)&k,   g_kb);
    cudaGetSymbolAddress((void**)&v,   g_vb);
    cudaGetSymbolAddress((void**)&part,g_part);
    cudaGetSymbolAddress((void**)&xh,  g_xh);  cudaGetSymbolAddress((void**)&xl, g_xl);
    cudaGetSymbolAddress((void**)&ah,  g_ah);  cudaGetSymbolAddress((void**)&al, g_al);
    cudaGetSymbolAddress((void**)&hh,  g_hh);  cudaGetSymbolAddress((void**)&hl, g_hl);
    cudaGetSymbolAddress((void**)&wqh, g_wqh); cudaGetSymbolAddress((void**)&wql, g_wql);
    cudaGetSymbolAddress((void**)&wkh, g_wkh); cudaGetSymbolAddress((void**)&wkl, g_wkl);
    cudaGetSymbolAddress((void**)&wvh, g_wvh); cudaGetSymbolAddress((void**)&wvl, g_wvl);
    cudaGetSymbolAddress((void**)&woh, g_woh); cudaGetSymbolAddress((void**)&wol, g_wol);
    cudaGetSymbolAddress((void**)&w1h, g_w1h); cudaGetSymbolAddress((void**)&w1l, g_w1l);
    cudaGetSymbolAddress((void**)&w2h, g_w2h); cudaGetSymbolAddress((void**)&w2l, g_w2l);

    // weight transpose + split (per call; inputs constant -> deterministic)
    {
        dim3 blk(32,8);
        convw_kernel<<<dim3(DM/32,  DM/32,  NLAYERS), blk>>>(Wq, wqh, wql, DM,  DM);
        convw_kernel<<<dim3(DM/32,  DM/32,  NLAYERS), blk>>>(Wk, wkh, wkl, DM,  DM);
        convw_kernel<<<dim3(DM/32,  DM/32,  NLAYERS), blk>>>(Wv, wvh, wvl, DM,  DM);
        convw_kernel<<<dim3(DM/32,  DM/32,  NLAYERS), blk>>>(Wo, woh, wol, DM,  DM);
        convw_kernel<<<dim3(DFF/32, DM/32,  NLAYERS), blk>>>(W1, w1h, w1l, DM,  DFF);
        convw_kernel<<<dim3(DM/32,  DFF/32, NLAYERS), blk>>>(W2, w2h, w2l, DFF, DM);
    }

    embed_kernel<<<NROWS, 256>>>(past_x, past_y, future_x, enc_W, enc_b, x, xh, xl);

    dim3 gQKV(DM/BN,  NROWS/BM, 3);    // 4 x 48 x 3
    dim3 gWo (DM/BN,  NROWS/BM, 2);    // split-K 2
    dim3 gFF (DFF/BN, NROWS/BM, 1);    // 32 x 48
    dim3 gW2 (DM/BN,  NROWS/BM, 4);    // split-K 4
    dim3 gA  (NCHUNK, NBH);

    const size_t PS = (size_t)NROWS*DM;

    for (int i=0;i<NLAYERS;i++){
        const size_t wo4 = (size_t)i*DM*DM;
        const size_t wo1 = (size_t)i*DM*DFF;

        qkv_bgemm<<<gQKV, 256>>>(xh, xl,
            wqh+wo4, wql+wo4, bq+i*DM,
            wkh+wo4, wkl+wo4, bk+i*DM,
            wvh+wo4, wvl+wo4, bv+i*DM,
            q, k, v);

        chunk_kv_kernel<<<gA, 1024>>>(k, v);
        attn_kernel<<<gA, 128>>>(q, k, v, ah, al);

        // Wo: split-K=2 raw partials, then fused residual+reduce+LN -> x (+split)
        bgemm_kernel<4><<<gWo, 256>>>(DM, DM, DM/2, ah, al,
            woh+wo4, wol+wo4, nullptr, part, nullptr, nullptr, PS);
        ln_red_kernel<<<NROWS, 256>>>(2, part, PS, x, bo+i*DM, ln1w+i*DM, ln1b+i*DM, x, xh, xl);

        // FFN
        bgemm_kernel<2><<<gFF, 256>>>(DM, DFF, DM, xh, xl,
            w1h+wo1, w1l+wo1, b1+i*DFF, nullptr, hh, hl, 0);
        bgemm_kernel<4><<<gW2, 256>>>(DFF, DM, DFF/4, hh, hl,
            w2h+wo1, w2l+wo1, nullptr, part, nullptr, nullptr, PS);
        ln_red_kernel<<<NROWS, 256>>>(4, part, PS, x, b2+i*DM, ln2w+i*DM, ln2b+i*DM, x, xh, xl);
    }

    head_kernel<<<BATCH*SFUT, 256>>>(x, mW, mb, sW, sb, (float*)d_out);
}